// round 1
// baseline (speedup 1.0000x reference)
#include <cuda_runtime.h>
#include <cuda_bf16.h>
#include <math.h>

#define NBATCH 4
#define NTOK   4096      // 8*8*8*8
#define DIM    512
#define MTOT   (NBATCH * NTOK)   // 16384
#define SM_SCALE 0.044194173824159216f   // 1/sqrt(512)

// ---------------- scratch (static device globals; no runtime alloc) ----------------
__device__ float g_Q[(size_t)NBATCH * NTOK * DIM];              // 32 MB
__device__ float g_K[(size_t)NBATCH * NTOK * DIM];              // 32 MB
__device__ float g_V[(size_t)NBATCH * NTOK * DIM];              // 32 MB
__device__ float g_S[(size_t)NBATCH * NTOK * NTOK];             // 256 MB

// ---------------- packed f32x2 helpers (sm_100+/sm_103a FFMA2 path) ----------------
__device__ __forceinline__ unsigned long long pack2_dup(float x) {
    unsigned long long r;
    unsigned int xi = __float_as_uint(x);
    asm("mov.b64 %0, {%1, %2};" : "=l"(r) : "r"(xi), "r"(xi));
    return r;
}
__device__ __forceinline__ void fma2(unsigned long long& d,
                                     unsigned long long a,
                                     unsigned long long b) {
    asm("fma.rn.f32x2 %0, %1, %2, %0;" : "+l"(d) : "l"(a), "l"(b));
}
__device__ __forceinline__ void unpack2(unsigned long long v, float& lo, float& hi) {
    unsigned int l, h;
    asm("mov.b64 {%0, %1}, %2;" : "=r"(l), "=r"(h) : "l"(v));
    lo = __uint_as_float(l);
    hi = __uint_as_float(h);
}

// ---------------- generic 128x128x8 SGEMM ----------------
// MODE 0: C = A @ B + bias          (A: MxK row-major, B: KxN row-major)
// MODE 1: C = (A @ B^T) * SM_SCALE  (A: MxK row-major, B: NxK row-major)
// MODE 2: C = A @ B                 (A: MxK row-major, B: KxN row-major)
template <int MODE>
__global__ __launch_bounds__(256, 2)
void sgemm_kernel(const float* __restrict__ Ag, const float* __restrict__ Bg,
                  const float* __restrict__ bias, float* __restrict__ Cg,
                  int M, int N, int K,
                  long long sA, long long sB, long long sC) {
    const int bz = blockIdx.z;
    const float* A = Ag + (long long)bz * sA;
    const float* B = Bg + (long long)bz * sB;
    float*       C = Cg + (long long)bz * sC;

    __shared__ __align__(16) float As[8][128];
    __shared__ __align__(16) float Bs[8][128];

    const int t  = threadIdx.x;
    const int tx = t & 15;   // column micro-tile index (x8)
    const int ty = t >> 4;   // row micro-tile index (x8)
    const int m0 = blockIdx.y * 128;
    const int n0 = blockIdx.x * 128;

    // A tile load mapping: 128 rows x 8 cols, one float4 per thread
    const int a_i  = t >> 1;
    const int a_j4 = (t & 1) * 4;
    // B (K-major) tile load mapping: 8 rows x 128 cols, one float4 per thread
    const int b_kk = t >> 5;
    const int b_j4 = (t & 31) * 4;
    // B^T (N-major) tile load mapping: like A
    const int bt_j  = t >> 1;
    const int bt_k4 = (t & 1) * 4;

    unsigned long long acc[8][4];
#pragma unroll
    for (int i = 0; i < 8; i++)
#pragma unroll
        for (int j = 0; j < 4; j++) acc[i][j] = 0ULL;

    for (int k0 = 0; k0 < K; k0 += 8) {
        // stage A transposed: As[kk][m]
        float4 av = *reinterpret_cast<const float4*>(
            &A[(long long)(m0 + a_i) * K + k0 + a_j4]);
        As[a_j4 + 0][a_i] = av.x;
        As[a_j4 + 1][a_i] = av.y;
        As[a_j4 + 2][a_i] = av.z;
        As[a_j4 + 3][a_i] = av.w;

        if (MODE == 1) {
            float4 bv = *reinterpret_cast<const float4*>(
                &B[(long long)(n0 + bt_j) * K + k0 + bt_k4]);
            Bs[bt_k4 + 0][bt_j] = bv.x;
            Bs[bt_k4 + 1][bt_j] = bv.y;
            Bs[bt_k4 + 2][bt_j] = bv.z;
            Bs[bt_k4 + 3][bt_j] = bv.w;
        } else {
            float4 bv = *reinterpret_cast<const float4*>(
                &B[(long long)(k0 + b_kk) * N + n0 + b_j4]);
            *reinterpret_cast<float4*>(&Bs[b_kk][b_j4]) = bv;
        }
        __syncthreads();

#pragma unroll
        for (int kk = 0; kk < 8; kk++) {
            float a[8];
#pragma unroll
            for (int i = 0; i < 8; i++) a[i] = As[kk][ty * 8 + i];
            unsigned long long b[4];
            const unsigned long long* bp =
                reinterpret_cast<const unsigned long long*>(&Bs[kk][tx * 8]);
#pragma unroll
            for (int j = 0; j < 4; j++) b[j] = bp[j];
#pragma unroll
            for (int i = 0; i < 8; i++) {
                unsigned long long aa = pack2_dup(a[i]);
#pragma unroll
                for (int j = 0; j < 4; j++) fma2(acc[i][j], aa, b[j]);
            }
        }
        __syncthreads();
    }

    // epilogue
#pragma unroll
    for (int i = 0; i < 8; i++) {
        float out[8];
#pragma unroll
        for (int j = 0; j < 4; j++) unpack2(acc[i][j], out[2 * j], out[2 * j + 1]);
        const int row = m0 + ty * 8 + i;
        const int col = n0 + tx * 8;
        if (MODE == 0) {
#pragma unroll
            for (int j = 0; j < 8; j++) out[j] += bias[col + j];
        } else if (MODE == 1) {
#pragma unroll
            for (int j = 0; j < 8; j++) out[j] *= SM_SCALE;
        }
        *reinterpret_cast<float4*>(&C[(long long)row * N + col]) =
            make_float4(out[0], out[1], out[2], out[3]);
        *reinterpret_cast<float4*>(&C[(long long)row * N + col + 4]) =
            make_float4(out[4], out[5], out[6], out[7]);
    }
}

// ---------------- row softmax over 4096 elements, in place ----------------
__global__ __launch_bounds__(256)
void softmax_kernel(float* __restrict__ S) {
    const size_t row = blockIdx.x;
    float* p = S + row * (size_t)NTOK;
    const int t = threadIdx.x;

    float v[16];
#pragma unroll
    for (int i = 0; i < 16; i++) v[i] = p[t + i * 256];

    float m = v[0];
#pragma unroll
    for (int i = 1; i < 16; i++) m = fmaxf(m, v[i]);

    __shared__ float red[256];
    red[t] = m;
    __syncthreads();
    for (int s = 128; s > 0; s >>= 1) {
        if (t < s) red[t] = fmaxf(red[t], red[t + s]);
        __syncthreads();
    }
    m = red[0];
    __syncthreads();

    float sum = 0.0f;
#pragma unroll
    for (int i = 0; i < 16; i++) {
        v[i] = __expf(v[i] - m);
        sum += v[i];
    }
    red[t] = sum;
    __syncthreads();
    for (int s = 128; s > 0; s >>= 1) {
        if (t < s) red[t] += red[t + s];
        __syncthreads();
    }
    const float inv = 1.0f / red[0];
#pragma unroll
    for (int i = 0; i < 16; i++) p[t + i * 256] = v[i] * inv;
}

// ---------------- launch ----------------
extern "C" void kernel_launch(void* const* d_in, const int* in_sizes, int n_in,
                              void* d_out, int out_size) {
    const float* qX  = (const float*)d_in[0];
    const float* kX  = (const float*)d_in[1];
    const float* vX  = (const float*)d_in[2];
    const float* W_Q = (const float*)d_in[3];
    const float* b_Q = (const float*)d_in[4];
    const float* W_K = (const float*)d_in[5];
    const float* b_K = (const float*)d_in[6];
    const float* W_V = (const float*)d_in[7];
    const float* b_V = (const float*)d_in[8];
    float* out = (float*)d_out;

    float *Q, *K, *V, *S;
    cudaGetSymbolAddress((void**)&Q, g_Q);
    cudaGetSymbolAddress((void**)&K, g_K);
    cudaGetSymbolAddress((void**)&V, g_V);
    cudaGetSymbolAddress((void**)&S, g_S);

    const long long sQKV = (long long)NTOK * DIM;
    const long long sS   = (long long)NTOK * NTOK;

    // 1) projections: (16384x512) @ (512x512) + bias
    {
        dim3 grid(DIM / 128, MTOT / 128, 1);
        sgemm_kernel<0><<<grid, 256>>>(qX, W_Q, b_Q, Q, MTOT, DIM, DIM, 0, 0, 0);
        sgemm_kernel<0><<<grid, 256>>>(kX, W_K, b_K, K, MTOT, DIM, DIM, 0, 0, 0);
        sgemm_kernel<0><<<grid, 256>>>(vX, W_V, b_V, V, MTOT, DIM, DIM, 0, 0, 0);
    }

    // 2) scores: S[b] = Q[b] @ K[b]^T * 1/sqrt(512)   (4096x4096x512, batched)
    {
        dim3 grid(NTOK / 128, NTOK / 128, NBATCH);
        sgemm_kernel<1><<<grid, 256>>>(Q, K, nullptr, S, NTOK, NTOK, DIM,
                                       sQKV, sQKV, sS);
    }

    // 3) softmax rows
    softmax_kernel<<<MTOT, 256>>>(S);

    // 4) output: out[b] = P[b] @ V[b]   (4096x512x4096, batched)
    {
        dim3 grid(DIM / 128, NTOK / 128, NBATCH);
        sgemm_kernel<2><<<grid, 256>>>(S, V, nullptr, out, NTOK, DIM, NTOK,
                                       sS, sQKV, sQKV);
    }
}

// round 3
// speedup vs baseline: 2.3558x; 2.3558x over previous
#include <cuda_runtime.h>
#include <cstdint>

#define NBATCH 4
#define NTOK   4096
#define DIM    512
#define MTOT   (NBATCH * NTOK)
#define SM_SCALE 0.044194173824159216f   // 1/sqrt(512)

// ---------------- scratch ----------------
__device__ float g_Q [(size_t)MTOT * DIM];            // 32 MB (pre-scaled by SM_SCALE)
__device__ float g_K [(size_t)MTOT * DIM];            // 32 MB
__device__ float g_Vt[(size_t)MTOT * DIM];            // 32 MB, per-batch [dim][tok]
__device__ float g_S [(size_t)NBATCH * NTOK * NTOK];  // 256 MB
__device__ float g_Wt[3ULL * DIM * DIM];              // 3 MB transposed weights

// round-to-nearest fp32 -> tf32 (unbiased)
__device__ __forceinline__ uint32_t tf32r(float x) {
    uint32_t r;
    asm("cvt.rna.tf32.f32 %0, %1;" : "=r"(r) : "f"(x));
    return r;
}

__device__ __forceinline__ void mma_tf32(float* d, const uint32_t* a, const uint32_t* b) {
    asm volatile(
        "mma.sync.aligned.m16n8k8.row.col.f32.tf32.tf32.f32 "
        "{%0,%1,%2,%3}, {%4,%5,%6,%7}, {%8,%9}, {%0,%1,%2,%3};"
        : "+f"(d[0]), "+f"(d[1]), "+f"(d[2]), "+f"(d[3])
        : "r"(a[0]), "r"(a[1]), "r"(a[2]), "r"(a[3]), "r"(b[0]), "r"(b[1]));
}

// ---------------- tiling constants ----------------
#define BM 128
#define BN 128
#define BK 32
#define LDS_STRIDE 40                        // floats per smem row (conflict-free frag loads)
#define TILE_U32   (128 * LDS_STRIDE)        // 5120 u32 per tile
#define SMEM_TOT   (4 * TILE_U32 * 4)        // 2 bufs x (A,B) = 81920 B

// ---------------- tf32 tensor-core GEMM: C[M,N] = alpha*(A @ B^T + bias) ----------------
// A: row-major [M x K] (lda). B: row-major [N x K] (ldb).
// Smem layout per row: within each 8-col k-group, values permuted to pairs (k, k+4):
//   [k0,k4,k1,k5,k2,k6,k3,k7] so fragment (b0,b1)/(a0,a2) loads are single LDS.64.
// VSTORE: write output transposed into per-batch [dim][tok] layout (for V projection).
template <bool BIAS, bool VSTORE>
__global__ __launch_bounds__(256, 2)
void gemm_mma(const float* __restrict__ Ag, const float* __restrict__ Bg,
              const float* __restrict__ bias, float* __restrict__ Cg,
              int N, int K, int lda, int ldb, float alpha,
              long long sA, long long sB, long long sC) {
    extern __shared__ uint32_t smu[];

    const int t    = threadIdx.x;
    const int lane = t & 31;
    const int w    = t >> 5;
    const int wm   = (w >> 2) * 64;   // warp row offset within CTA tile
    const int wn   = (w & 3) * 32;    // warp col offset
    const int m0   = blockIdx.y * BM;
    const int n0   = blockIdx.x * BN;
    const int bz   = blockIdx.z;

    const float* A = Ag + (long long)bz * sA;
    const float* B = Bg + (long long)bz * sB;

    // staging: thread handles one row, 16 contiguous floats (two 8-col k-groups)
    const int srow = t >> 1;
    const int scb  = (t & 1) * 16;
    const float* Aptr = A + (long long)(m0 + srow) * lda + scb;
    const float* Bptr = B + (long long)(n0 + srow) * ldb + scb;

    float acc[4][4][4];
#pragma unroll
    for (int i = 0; i < 4; i++)
#pragma unroll
        for (int j = 0; j < 4; j++)
#pragma unroll
            for (int q = 0; q < 4; q++) acc[i][j][q] = 0.0f;

    float4 pa[4], pb[4];

    auto prefetch = [&](int k0) {
#pragma unroll
        for (int i = 0; i < 4; i++) {
            pa[i] = *reinterpret_cast<const float4*>(Aptr + k0 + i * 4);
            pb[i] = *reinterpret_cast<const float4*>(Bptr + k0 + i * 4);
        }
    };
    // store one 8-col group as pairs (k,k+4): [lo.x,hi.x,lo.y,hi.y][lo.z,hi.z,lo.w,hi.w]
    auto stash = [&](uint32_t* base, float4 lo, float4 hi, int col) {
        uint32_t* p = base + srow * LDS_STRIDE + col;
        *reinterpret_cast<uint4*>(p) =
            make_uint4(tf32r(lo.x), tf32r(hi.x), tf32r(lo.y), tf32r(hi.y));
        *reinterpret_cast<uint4*>(p + 4) =
            make_uint4(tf32r(lo.z), tf32r(hi.z), tf32r(lo.w), tf32r(hi.w));
    };
    auto stage = [&](int buf) {
        uint32_t* As = smu + buf * (2 * TILE_U32);
        uint32_t* Bs = As + TILE_U32;
        stash(As, pa[0], pa[1], scb);
        stash(As, pa[2], pa[3], scb + 8);
        stash(Bs, pb[0], pb[1], scb);
        stash(Bs, pb[2], pb[3], scb + 8);
    };

    prefetch(0);
    stage(0);
    __syncthreads();

    const int nchunk = K >> 5;
    const int fr = lane >> 2;          // fragment row within atom
    const int fp = 2 * (lane & 3);     // pair offset within k-group

    for (int c = 0; c < nchunk; c++) {
        const int cur = c & 1;
        if (c + 1 < nchunk) prefetch((c + 1) * BK);

        const uint32_t* As = smu + cur * (2 * TILE_U32);
        const uint32_t* Bs = As + TILE_U32;

#pragma unroll
        for (int ks = 0; ks < 4; ks++) {
            const int colb = ks * 8 + fp;
            uint32_t afr[4][4], bfr[4][2];
#pragma unroll
            for (int ma = 0; ma < 4; ma++) {
                const int r = wm + ma * 16 + fr;
                uint2 lo = *reinterpret_cast<const uint2*>(As + r * LDS_STRIDE + colb);
                uint2 hi = *reinterpret_cast<const uint2*>(As + (r + 8) * LDS_STRIDE + colb);
                afr[ma][0] = lo.x; afr[ma][2] = lo.y;   // (k, k+4) on row r
                afr[ma][1] = hi.x; afr[ma][3] = hi.y;   // (k, k+4) on row r+8
            }
#pragma unroll
            for (int na = 0; na < 4; na++) {
                const int n = wn + na * 8 + fr;
                uint2 v = *reinterpret_cast<const uint2*>(Bs + n * LDS_STRIDE + colb);
                bfr[na][0] = v.x; bfr[na][1] = v.y;
            }
#pragma unroll
            for (int ma = 0; ma < 4; ma++)
#pragma unroll
                for (int na = 0; na < 4; na++)
                    mma_tf32(acc[ma][na], afr[ma], bfr[na]);
        }

        if (c + 1 < nchunk) stage(cur ^ 1);
        __syncthreads();
    }

    // ---------------- epilogue ----------------
#pragma unroll
    for (int ma = 0; ma < 4; ma++) {
        const int r0 = m0 + wm + ma * 16 + fr;
#pragma unroll
        for (int na = 0; na < 4; na++) {
            const int col = n0 + wn + na * 8 + fp;
            float v0 = acc[ma][na][0], v1 = acc[ma][na][1];
            float v2 = acc[ma][na][2], v3 = acc[ma][na][3];
            if (BIAS) {
                const float b0 = bias[col], b1 = bias[col + 1];
                v0 += b0; v1 += b1; v2 += b0; v3 += b1;
            }
            v0 *= alpha; v1 *= alpha; v2 *= alpha; v3 *= alpha;
            if (VSTORE) {
                // per-batch transposed: out[b][dim][tok]
                const int tok0 = r0 & (NTOK - 1), tok1 = (r0 + 8) & (NTOK - 1);
                float* o = Cg + (long long)(r0 >> 12) * ((long long)DIM * NTOK);
                o[(long long)col * NTOK + tok0]       = v0;
                o[(long long)(col + 1) * NTOK + tok0] = v1;
                o[(long long)col * NTOK + tok1]       = v2;
                o[(long long)(col + 1) * NTOK + tok1] = v3;
            } else {
                float* o = Cg + (long long)bz * sC;
                *reinterpret_cast<float2*>(o + (long long)r0 * N + col)       = make_float2(v0, v1);
                *reinterpret_cast<float2*>(o + (long long)(r0 + 8) * N + col) = make_float2(v2, v3);
            }
        }
    }
}

// ---------------- 512x512 transpose (weights) ----------------
__global__ void transpose512(const float* __restrict__ in, float* __restrict__ out) {
    __shared__ float tile[32][33];
    int x = blockIdx.x * 32 + threadIdx.x;
    int y0 = blockIdx.y * 32;
#pragma unroll
    for (int j = threadIdx.y; j < 32; j += 8)
        tile[j][threadIdx.x] = in[(size_t)(y0 + j) * 512 + x];
    __syncthreads();
    int ox = y0 + threadIdx.x;
    int oy0 = blockIdx.x * 32;
#pragma unroll
    for (int j = threadIdx.y; j < 32; j += 8)
        out[(size_t)(oy0 + j) * 512 + ox] = tile[threadIdx.x][j];
}

// ---------------- row softmax over 4096, in place ----------------
__global__ __launch_bounds__(256)
void softmax_kernel(float* __restrict__ S) {
    const size_t row = blockIdx.x;
    float* p = S + row * (size_t)NTOK;
    const int t = threadIdx.x;
    float v[16];
#pragma unroll
    for (int i = 0; i < 16; i++) v[i] = p[t + i * 256];
    float m = v[0];
#pragma unroll
    for (int i = 1; i < 16; i++) m = fmaxf(m, v[i]);
    __shared__ float red[256];
    red[t] = m; __syncthreads();
    for (int s = 128; s > 0; s >>= 1) { if (t < s) red[t] = fmaxf(red[t], red[t + s]); __syncthreads(); }
    m = red[0]; __syncthreads();
    float sum = 0.f;
#pragma unroll
    for (int i = 0; i < 16; i++) { v[i] = __expf(v[i] - m); sum += v[i]; }
    red[t] = sum; __syncthreads();
    for (int s = 128; s > 0; s >>= 1) { if (t < s) red[t] += red[t + s]; __syncthreads(); }
    const float inv = 1.0f / red[0];
#pragma unroll
    for (int i = 0; i < 16; i++) p[t + i * 256] = v[i] * inv;
}

// ---------------- launch ----------------
extern "C" void kernel_launch(void* const* d_in, const int* in_sizes, int n_in,
                              void* d_out, int out_size) {
    const float* qX  = (const float*)d_in[0];
    const float* kX  = (const float*)d_in[1];
    const float* vX  = (const float*)d_in[2];
    const float* W_Q = (const float*)d_in[3];
    const float* b_Q = (const float*)d_in[4];
    const float* W_K = (const float*)d_in[5];
    const float* b_K = (const float*)d_in[6];
    const float* W_V = (const float*)d_in[7];
    const float* b_V = (const float*)d_in[8];
    float* out = (float*)d_out;

    float *Q, *K, *Vt, *S, *Wt;
    cudaGetSymbolAddress((void**)&Q,  g_Q);
    cudaGetSymbolAddress((void**)&K,  g_K);
    cudaGetSymbolAddress((void**)&Vt, g_Vt);
    cudaGetSymbolAddress((void**)&S,  g_S);
    cudaGetSymbolAddress((void**)&Wt, g_Wt);

    cudaFuncSetAttribute(gemm_mma<true,  false>, cudaFuncAttributeMaxDynamicSharedMemorySize, SMEM_TOT);
    cudaFuncSetAttribute(gemm_mma<true,  true >, cudaFuncAttributeMaxDynamicSharedMemorySize, SMEM_TOT);
    cudaFuncSetAttribute(gemm_mma<false, false>, cudaFuncAttributeMaxDynamicSharedMemorySize, SMEM_TOT);

    const long long sQKV = (long long)NTOK * DIM;
    const long long sS   = (long long)NTOK * NTOK;

    // 0) weight transposes (B operand must be [N x K] K-major)
    {
        dim3 g(16, 16), b(32, 8);
        transpose512<<<g, b>>>(W_Q, Wt);
        transpose512<<<g, b>>>(W_K, Wt + (size_t)DIM * DIM);
        transpose512<<<g, b>>>(W_V, Wt + 2 * (size_t)DIM * DIM);
    }

    // 1) projections (Q pre-scaled by 1/sqrt(d)); V written transposed per batch
    {
        dim3 grid(DIM / BN, MTOT / BM, 1);
        gemm_mma<true, false><<<grid, 256, SMEM_TOT>>>(qX, Wt, b_Q, Q,
            DIM, DIM, DIM, DIM, SM_SCALE, 0, 0, 0);
        gemm_mma<true, false><<<grid, 256, SMEM_TOT>>>(kX, Wt + (size_t)DIM * DIM, b_K, K,
            DIM, DIM, DIM, DIM, 1.0f, 0, 0, 0);
        gemm_mma<true, true><<<grid, 256, SMEM_TOT>>>(vX, Wt + 2 * (size_t)DIM * DIM, b_V, Vt,
            DIM, DIM, DIM, DIM, 1.0f, 0, 0, 0);
    }

    // 2) scores: S[b] = Q[b] @ K[b]^T (scale folded into Q)
    {
        dim3 grid(NTOK / BN, NTOK / BM, NBATCH);
        gemm_mma<false, false><<<grid, 256, SMEM_TOT>>>(Q, K, nullptr, S,
            NTOK, DIM, DIM, DIM, 1.0f, sQKV, sQKV, sS);
    }

    // 3) softmax
    softmax_kernel<<<MTOT, 256>>>(S);

    // 4) out[b] = P[b] @ Vt[b]^T  (Vt per batch is [dim][tok] -> B is [512 x 4096] K-major)
    {
        dim3 grid(DIM / BN, NTOK / BM, NBATCH);
        gemm_mma<false, false><<<grid, 256, SMEM_TOT>>>(S, Vt, nullptr, out,
            DIM, NTOK, NTOK, NTOK, 1.0f, sS, sQKV, sQKV);
    }
}

// round 4
// speedup vs baseline: 2.4505x; 1.0402x over previous
#include <cuda_runtime.h>
#include <cstdint>

#define NBATCH 4
#define NTOK   4096
#define DIM    512
#define MTOT   (NBATCH * NTOK)
#define SM_SCALE 0.044194173824159216f   // 1/sqrt(512)

// ---------------- scratch ----------------
__device__ float g_Q [(size_t)MTOT * DIM];            // 32 MB (pre-scaled by SM_SCALE)
__device__ float g_K [(size_t)MTOT * DIM];            // 32 MB
__device__ float g_Vt[(size_t)MTOT * DIM];            // 32 MB, per-batch [dim][tok]
__device__ float g_S [(size_t)NBATCH * NTOK * NTOK];  // 256 MB
__device__ float g_Wt[3ULL * DIM * DIM];              // 3 MB transposed weights

// ---------------- mma + async helpers ----------------
__device__ __forceinline__ void mma_tf32(float* d, const uint32_t* a, const uint32_t* b) {
    asm volatile(
        "mma.sync.aligned.m16n8k8.row.col.f32.tf32.tf32.f32 "
        "{%0,%1,%2,%3}, {%4,%5,%6,%7}, {%8,%9}, {%0,%1,%2,%3};"
        : "+f"(d[0]), "+f"(d[1]), "+f"(d[2]), "+f"(d[3])
        : "r"(a[0]), "r"(a[1]), "r"(a[2]), "r"(a[3]), "r"(b[0]), "r"(b[1]));
}
__device__ __forceinline__ uint32_t smem_u32(const void* p) {
    uint32_t r;
    asm("{ .reg .u64 t; cvta.to.shared.u64 t, %1; cvt.u32.u64 %0, t; }" : "=r"(r) : "l"(p));
    return r;
}
__device__ __forceinline__ void cpa16(uint32_t dst, const void* src) {
    asm volatile("cp.async.cg.shared.global [%0], [%1], 16;" :: "r"(dst), "l"(src));
}
#define CP_COMMIT() asm volatile("cp.async.commit_group;" ::: "memory")
#define CP_WAIT1()  asm volatile("cp.async.wait_group 1;" ::: "memory")

// ---------------- tiling ----------------
#define BM 128
#define BN 128
#define BK 32
#define STR 36                         // floats per smem row (conflict-free LDS.32)
#define TILE_F (128 * STR)             // floats per tile
#define STAGE_F (2 * TILE_F)           // A + B
#define SMEM_TOT (2 * STAGE_F * 4)     // 2 stages = 73728 B

// ---------------- tf32 tensor-core GEMM: C[M,N] = alpha*(A @ B^T + bias) ----------------
// A: row-major [M x K] (lda). B: row-major [N x K] (ldb). Raw fp32 staged; HW truncates to tf32.
// 4 warps, warp tile 64x64 (ma=4 atoms x 16, na=8 atoms x 8).
// VSTORE: write output transposed into per-batch [dim][tok] layout (V projection).
template <bool BIAS, bool VSTORE>
__global__ __launch_bounds__(128, 2)
void gemm_mma(const float* __restrict__ Ag, const float* __restrict__ Bg,
              const float* __restrict__ bias, float* __restrict__ Cg,
              int N, int K, int lda, int ldb, float alpha,
              long long sA, long long sB, long long sC) {
    extern __shared__ float smf[];
    const uint32_t sbase = smem_u32(smf);

    const int t    = threadIdx.x;
    const int lane = t & 31;
    const int w    = t >> 5;
    const int wm   = (w & 1) * 64;
    const int wn   = (w >> 1) * 64;
    const int m0   = blockIdx.y * BM;
    const int n0   = blockIdx.x * BN;
    const int bz   = blockIdx.z;

    const float* A = Ag + (long long)bz * sA;
    const float* B = Bg + (long long)bz * sB;

    // staging roles: warp w copies rows [w*32, w*32+32) of each tile;
    // lane: srow = lane>>3 (4 rows/instr), sseg = lane&7 (16B segments) -> fully coalesced
    const int srow = lane >> 3;
    const int sseg = lane & 7;
    const float* Aptr = A + (long long)(m0 + w * 32 + srow) * lda + sseg * 4;
    const float* Bptr = B + (long long)(n0 + w * 32 + srow) * ldb + sseg * 4;
    const uint32_t sd = (uint32_t)(((w * 32 + srow) * STR + sseg * 4) * 4);

    auto issue = [&](int c, int buf) {
        const int k0 = c * BK;
        const uint32_t da = sbase + (uint32_t)buf * (STAGE_F * 4) + sd;
        const uint32_t db = da + TILE_F * 4;
#pragma unroll
        for (int it = 0; it < 8; it++) {
            cpa16(da + it * 4 * STR * 4, Aptr + (long long)it * 4 * lda + k0);
            cpa16(db + it * 4 * STR * 4, Bptr + (long long)it * 4 * ldb + k0);
        }
    };

    float acc[4][8][4];
#pragma unroll
    for (int i = 0; i < 4; i++)
#pragma unroll
        for (int j = 0; j < 8; j++)
#pragma unroll
            for (int q = 0; q < 4; q++) acc[i][j][q] = 0.0f;

    const int nchunk = K >> 5;
    issue(0, 0); CP_COMMIT();
    issue(1, 1); CP_COMMIT();

    const int fr = lane >> 2;
    const int fj = lane & 3;

    for (int c = 0; c < nchunk; c++) {
        const int buf = c & 1;
        CP_WAIT1();
        __syncthreads();

        const uint32_t* As = reinterpret_cast<const uint32_t*>(smf) + buf * STAGE_F;
        const uint32_t* Bs = As + TILE_F;

#pragma unroll
        for (int ks = 0; ks < 4; ks++) {
            const int kb = ks * 8 + fj;
            uint32_t afr[4][4], bfr[8][2];
#pragma unroll
            for (int ma = 0; ma < 4; ma++) {
                const int r = wm + ma * 16 + fr;
                afr[ma][0] = As[r * STR + kb];
                afr[ma][1] = As[(r + 8) * STR + kb];
                afr[ma][2] = As[r * STR + kb + 4];
                afr[ma][3] = As[(r + 8) * STR + kb + 4];
            }
#pragma unroll
            for (int na = 0; na < 8; na++) {
                const int n = wn + na * 8 + fr;
                bfr[na][0] = Bs[n * STR + kb];
                bfr[na][1] = Bs[n * STR + kb + 4];
            }
#pragma unroll
            for (int ma = 0; ma < 4; ma++)
#pragma unroll
                for (int na = 0; na < 8; na++)
                    mma_tf32(acc[ma][na], afr[ma], bfr[na]);
        }

        __syncthreads();
        if (c + 2 < nchunk) issue(c + 2, buf);
        CP_COMMIT();
    }

    // ---------------- epilogue ----------------
    const int fp = 2 * fj;
#pragma unroll
    for (int ma = 0; ma < 4; ma++) {
        const int r0 = m0 + wm + ma * 16 + fr;
#pragma unroll
        for (int na = 0; na < 8; na++) {
            const int col = n0 + wn + na * 8 + fp;
            float v0 = acc[ma][na][0], v1 = acc[ma][na][1];
            float v2 = acc[ma][na][2], v3 = acc[ma][na][3];
            if (BIAS) {
                const float b0 = bias[col], b1 = bias[col + 1];
                v0 += b0; v1 += b1; v2 += b0; v3 += b1;
            }
            v0 *= alpha; v1 *= alpha; v2 *= alpha; v3 *= alpha;
            if (VSTORE) {
                const int tok0 = r0 & (NTOK - 1), tok1 = (r0 + 8) & (NTOK - 1);
                float* o = Cg + (long long)(r0 >> 12) * ((long long)DIM * NTOK);
                o[(long long)col * NTOK + tok0]       = v0;
                o[(long long)(col + 1) * NTOK + tok0] = v1;
                o[(long long)col * NTOK + tok1]       = v2;
                o[(long long)(col + 1) * NTOK + tok1] = v3;
            } else {
                float* o = Cg + (long long)bz * sC;
                *reinterpret_cast<float2*>(o + (long long)r0 * N + col)       = make_float2(v0, v1);
                *reinterpret_cast<float2*>(o + (long long)(r0 + 8) * N + col) = make_float2(v2, v3);
            }
        }
    }
}

// ---------------- 512x512 transpose (weights) ----------------
__global__ void transpose512(const float* __restrict__ in, float* __restrict__ out) {
    __shared__ float tile[32][33];
    int x = blockIdx.x * 32 + threadIdx.x;
    int y0 = blockIdx.y * 32;
#pragma unroll
    for (int j = threadIdx.y; j < 32; j += 8)
        tile[j][threadIdx.x] = in[(size_t)(y0 + j) * 512 + x];
    __syncthreads();
    int ox = y0 + threadIdx.x;
    int oy0 = blockIdx.x * 32;
#pragma unroll
    for (int j = threadIdx.y; j < 32; j += 8)
        out[(size_t)(oy0 + j) * 512 + ox] = tile[threadIdx.x][j];
}

// ---------------- row softmax over 4096, in place ----------------
__global__ __launch_bounds__(256)
void softmax_kernel(float* __restrict__ S) {
    const size_t row = blockIdx.x;
    float* p = S + row * (size_t)NTOK;
    const int t = threadIdx.x;
    float v[16];
#pragma unroll
    for (int i = 0; i < 16; i++) v[i] = p[t + i * 256];
    float m = v[0];
#pragma unroll
    for (int i = 1; i < 16; i++) m = fmaxf(m, v[i]);
    __shared__ float red[256];
    red[t] = m; __syncthreads();
    for (int s = 128; s > 0; s >>= 1) { if (t < s) red[t] = fmaxf(red[t], red[t + s]); __syncthreads(); }
    m = red[0]; __syncthreads();
    float sum = 0.f;
#pragma unroll
    for (int i = 0; i < 16; i++) { v[i] = __expf(v[i] - m); sum += v[i]; }
    red[t] = sum; __syncthreads();
    for (int s = 128; s > 0; s >>= 1) { if (t < s) red[t] += red[t + s]; __syncthreads(); }
    const float inv = 1.0f / red[0];
#pragma unroll
    for (int i = 0; i < 16; i++) p[t + i * 256] = v[i] * inv;
}

// ---------------- launch ----------------
extern "C" void kernel_launch(void* const* d_in, const int* in_sizes, int n_in,
                              void* d_out, int out_size) {
    const float* qX  = (const float*)d_in[0];
    const float* kX  = (const float*)d_in[1];
    const float* vX  = (const float*)d_in[2];
    const float* W_Q = (const float*)d_in[3];
    const float* b_Q = (const float*)d_in[4];
    const float* W_K = (const float*)d_in[5];
    const float* b_K = (const float*)d_in[6];
    const float* W_V = (const float*)d_in[7];
    const float* b_V = (const float*)d_in[8];
    float* out = (float*)d_out;

    float *Q, *K, *Vt, *S, *Wt;
    cudaGetSymbolAddress((void**)&Q,  g_Q);
    cudaGetSymbolAddress((void**)&K,  g_K);
    cudaGetSymbolAddress((void**)&Vt, g_Vt);
    cudaGetSymbolAddress((void**)&S,  g_S);
    cudaGetSymbolAddress((void**)&Wt, g_Wt);

    cudaFuncSetAttribute(gemm_mma<true,  false>, cudaFuncAttributeMaxDynamicSharedMemorySize, SMEM_TOT);
    cudaFuncSetAttribute(gemm_mma<true,  true >, cudaFuncAttributeMaxDynamicSharedMemorySize, SMEM_TOT);
    cudaFuncSetAttribute(gemm_mma<false, false>, cudaFuncAttributeMaxDynamicSharedMemorySize, SMEM_TOT);

    const long long sQKV = (long long)NTOK * DIM;
    const long long sS   = (long long)NTOK * NTOK;

    // 0) weight transposes (B operand must be [N x K] K-major)
    {
        dim3 g(16, 16), b(32, 8);
        transpose512<<<g, b>>>(W_Q, Wt);
        transpose512<<<g, b>>>(W_K, Wt + (size_t)DIM * DIM);
        transpose512<<<g, b>>>(W_V, Wt + 2 * (size_t)DIM * DIM);
    }

    // 1) projections (Q pre-scaled by 1/sqrt(d)); V written transposed per batch
    {
        dim3 grid(DIM / BN, MTOT / BM, 1);
        gemm_mma<true, false><<<grid, 128, SMEM_TOT>>>(qX, Wt, b_Q, Q,
            DIM, DIM, DIM, DIM, SM_SCALE, 0, 0, 0);
        gemm_mma<true, false><<<grid, 128, SMEM_TOT>>>(kX, Wt + (size_t)DIM * DIM, b_K, K,
            DIM, DIM, DIM, DIM, 1.0f, 0, 0, 0);
        gemm_mma<true, true><<<grid, 128, SMEM_TOT>>>(vX, Wt + 2 * (size_t)DIM * DIM, b_V, Vt,
            DIM, DIM, DIM, DIM, 1.0f, 0, 0, 0);
    }

    // 2) scores: S[b] = Q[b] @ K[b]^T (scale folded into Q)
    {
        dim3 grid(NTOK / BN, NTOK / BM, NBATCH);
        gemm_mma<false, false><<<grid, 128, SMEM_TOT>>>(Q, K, nullptr, S,
            NTOK, DIM, DIM, DIM, 1.0f, sQKV, sQKV, sS);
    }

    // 3) softmax
    softmax_kernel<<<MTOT, 256>>>(S);

    // 4) out[b] = P[b] @ Vt[b]^T  (Vt per batch is [dim][tok] -> B is [512 x 4096] K-major)
    {
        dim3 grid(DIM / BN, NTOK / BM, NBATCH);
        gemm_mma<false, false><<<grid, 128, SMEM_TOT>>>(S, Vt, nullptr, out,
            DIM, NTOK, NTOK, NTOK, 1.0f, sS, sQKV, sQKV);
    }
}

// round 5
// speedup vs baseline: 3.2258x; 1.3164x over previous
#include <cuda_runtime.h>
#include <cstdint>

#define NBATCH 4
#define NTOK   4096
#define DIM    512
#define MTOT   (NBATCH * NTOK)
#define SM_SCALE 0.044194173824159216f   // 1/sqrt(512)

// ---------------- scratch ----------------
__device__ float g_Q [(size_t)MTOT * DIM];            // 32 MB tf32, dim-permuted, pre-scaled
__device__ float g_K [(size_t)MTOT * DIM];            // 32 MB tf32, dim-permuted
__device__ float g_Vt[(size_t)MTOT * DIM];            // 32 MB tf32, [dim][tok], tok-permuted
__device__ float g_S [(size_t)NBATCH * NTOK * NTOK];  // 268 MB (also hosts rna'd inputs pre-scores)
__device__ float g_Wt[3ULL * DIM * DIM];              // 3 MB tf32, transposed + id-permuted

// ---------------- helpers ----------------
__device__ __forceinline__ uint32_t tf32r(float x) {   // round-to-nearest tf32
    uint32_t r;
    asm("cvt.rna.tf32.f32 %0, %1;" : "=r"(r) : "f"(x));
    return r;
}
__device__ __forceinline__ float tf32rf(float x) { return __uint_as_float(tf32r(x)); }
__device__ __forceinline__ int perm8(int j) {          // storage position of logical k-index j
    return (j & 4) ? (((j & 3) << 1) | 1) : (j << 1);
}
__device__ __forceinline__ void mma_tf32(float* d, const uint32_t* a, const uint32_t* b) {
    asm volatile(
        "mma.sync.aligned.m16n8k8.row.col.f32.tf32.tf32.f32 "
        "{%0,%1,%2,%3}, {%4,%5,%6,%7}, {%8,%9}, {%0,%1,%2,%3};"
        : "+f"(d[0]), "+f"(d[1]), "+f"(d[2]), "+f"(d[3])
        : "r"(a[0]), "r"(a[1]), "r"(a[2]), "r"(a[3]), "r"(b[0]), "r"(b[1]));
}
__device__ __forceinline__ uint32_t smem_u32(const void* p) {
    uint32_t r;
    asm("{ .reg .u64 t; cvta.to.shared.u64 t, %1; cvt.u32.u64 %0, t; }" : "=r"(r) : "l"(p));
    return r;
}
__device__ __forceinline__ void cpa16(uint32_t dst, const void* src) {
    asm volatile("cp.async.cg.shared.global [%0], [%1], 16;" :: "r"(dst), "l"(src));
}
#define CP_COMMIT() asm volatile("cp.async.commit_group;" ::: "memory")
#define CP_WAIT1()  asm volatile("cp.async.wait_group 1;" ::: "memory")

// ---------------- tiling ----------------
#define BM 128
#define BN 128
#define BK 32
#define STR 36
#define TILE_F (128 * STR)
#define STAGE_F (2 * TILE_F)
#define SMEM_TOT (2 * STAGE_F * 4)     // 73728 B

// ---------------- tf32 tensor-core GEMM: C[M,N] = alpha*(A @ B^T + bias) ----------------
// A,B row-major K-major, stored tf32 + k-pair-permuted (pairs (k,k+4) contiguous).
// OM: 0 = plain fp32 out; 1 = col-perm + rna (Q/K proj); 2 = col-perm (scores S);
//     3 = transposed [dim][tok] store, tok-perm + rna (V proj).
template <bool BIAS, int OM>
__global__ __launch_bounds__(128, 2)
void gemm_mma(const float* __restrict__ Ag, const float* __restrict__ Bg,
              const float* __restrict__ bias, float* __restrict__ Cg,
              int N, int K, int lda, int ldb, float alpha,
              long long sA, long long sB, long long sC) {
    extern __shared__ float smf[];
    const uint32_t sbase = smem_u32(smf);

    const int t    = threadIdx.x;
    const int lane = t & 31;
    const int w    = t >> 5;
    const int wm   = (w & 1) * 64;
    const int wn   = (w >> 1) * 64;
    const int m0   = blockIdx.y * BM;
    const int n0   = blockIdx.x * BN;
    const int bz   = blockIdx.z;

    const float* A = Ag + (long long)bz * sA;
    const float* B = Bg + (long long)bz * sB;

    const int srow = lane >> 3;
    const int sseg = lane & 7;
    const float* Aptr = A + (long long)(m0 + w * 32 + srow) * lda + sseg * 4;
    const float* Bptr = B + (long long)(n0 + w * 32 + srow) * ldb + sseg * 4;
    const uint32_t sd = (uint32_t)(((w * 32 + srow) * STR + sseg * 4) * 4);

    auto issue = [&](int c, int buf) {
        const int k0 = c * BK;
        const uint32_t da = sbase + (uint32_t)buf * (STAGE_F * 4) + sd;
        const uint32_t db = da + TILE_F * 4;
#pragma unroll
        for (int it = 0; it < 8; it++) {
            cpa16(da + it * 4 * STR * 4, Aptr + (long long)it * 4 * lda + k0);
            cpa16(db + it * 4 * STR * 4, Bptr + (long long)it * 4 * ldb + k0);
        }
    };

    float acc[4][8][4];
#pragma unroll
    for (int i = 0; i < 4; i++)
#pragma unroll
        for (int j = 0; j < 8; j++)
#pragma unroll
            for (int q = 0; q < 4; q++) acc[i][j][q] = 0.0f;

    const int nchunk = K >> 5;
    issue(0, 0); CP_COMMIT();
    issue(1, 1); CP_COMMIT();

    const int fr = lane >> 2;
    const int fj = lane & 3;

    for (int c = 0; c < nchunk; c++) {
        const int buf = c & 1;
        CP_WAIT1();
        __syncthreads();

        const uint32_t* As = reinterpret_cast<const uint32_t*>(smf) + buf * STAGE_F;
        const uint32_t* Bs = As + TILE_F;

#pragma unroll
        for (int ks = 0; ks < 4; ks++) {
            const int kb2 = ks * 8 + 2 * fj;       // permuted pair offset: (k, k+4) contiguous
            uint32_t afr[4][4], bfr[8][2];
#pragma unroll
            for (int ma = 0; ma < 4; ma++) {
                const int r = wm + ma * 16 + fr;
                uint2 lo = *reinterpret_cast<const uint2*>(As + r * STR + kb2);
                uint2 hi = *reinterpret_cast<const uint2*>(As + (r + 8) * STR + kb2);
                afr[ma][0] = lo.x; afr[ma][2] = lo.y;
                afr[ma][1] = hi.x; afr[ma][3] = hi.y;
            }
#pragma unroll
            for (int na = 0; na < 8; na++) {
                const int n = wn + na * 8 + fr;
                uint2 v = *reinterpret_cast<const uint2*>(Bs + n * STR + kb2);
                bfr[na][0] = v.x; bfr[na][1] = v.y;
            }
#pragma unroll
            for (int ma = 0; ma < 4; ma++)
#pragma unroll
                for (int na = 0; na < 8; na++)
                    mma_tf32(acc[ma][na], afr[ma], bfr[na]);
        }

        __syncthreads();
        if (c + 2 < nchunk) issue(c + 2, buf);
        CP_COMMIT();
    }

    // ---------------- epilogue ----------------
    const int fp = 2 * fj;                                    // logical col offset (even)
#pragma unroll
    for (int ma = 0; ma < 4; ma++) {
        const int r0 = m0 + wm + ma * 16 + fr;
#pragma unroll
        for (int na = 0; na < 8; na++) {
            const int col = n0 + wn + na * 8 + fp;            // logical col (even)
            float v0 = acc[ma][na][0], v1 = acc[ma][na][1];
            float v2 = acc[ma][na][2], v3 = acc[ma][na][3];
            if (BIAS) {
                const float b0 = bias[col], b1 = bias[col + 1];
                v0 += b0; v1 += b1; v2 += b0; v3 += b1;
            }
            v0 *= alpha; v1 *= alpha; v2 *= alpha; v3 *= alpha;

            if (OM == 3) {
                // transposed store: out[b][dim=col][tok'], tok position permuted, rna
                const int tok0 = ((r0 & (NTOK - 1)) & ~7) | perm8(r0 & 7);
                const int tok1 = tok0 + 8;                    // (r0+8) same in-group index
                float* o = Cg + (long long)(r0 >> 12) * ((long long)DIM * NTOK);
                o[(long long)col * NTOK + tok0]       = tf32rf(v0);
                o[(long long)(col + 1) * NTOK + tok0] = tf32rf(v1);
                o[(long long)col * NTOK + tok1]       = tf32rf(v2);
                o[(long long)(col + 1) * NTOK + tok1] = tf32rf(v3);
            } else if (OM == 1 || OM == 2) {
                // col-permuted: logical col -> scol, col+1 -> scol+2
                const int scol = (col & ~7) | perm8(col & 7);
                if (OM == 1) { v0 = tf32rf(v0); v1 = tf32rf(v1); v2 = tf32rf(v2); v3 = tf32rf(v3); }
                float* o = Cg + (long long)bz * sC;
                o[(long long)r0 * N + scol]           = v0;
                o[(long long)r0 * N + scol + 2]       = v1;
                o[(long long)(r0 + 8) * N + scol]     = v2;
                o[(long long)(r0 + 8) * N + scol + 2] = v3;
            } else {
                float* o = Cg + (long long)bz * sC;
                *reinterpret_cast<float2*>(o + (long long)r0 * N + col)       = make_float2(v0, v1);
                *reinterpret_cast<float2*>(o + (long long)(r0 + 8) * N + col) = make_float2(v2, v3);
            }
        }
    }
}

// ---------------- input prepass: rna to tf32 + k-pair permute (8 floats / thread) ----------------
__global__ __launch_bounds__(256)
void prep_rna_perm(const float* __restrict__ in, float* __restrict__ out, int n8) {
    int i = blockIdx.x * 256 + threadIdx.x;
    if (i >= n8) return;
    const float4* p = reinterpret_cast<const float4*>(in) + 2 * (size_t)i;
    float4 a = p[0], b = p[1];
    float4* o = reinterpret_cast<float4*>(out) + 2 * (size_t)i;
    o[0] = make_float4(tf32rf(a.x), tf32rf(b.x), tf32rf(a.y), tf32rf(b.y));
    o[1] = make_float4(tf32rf(a.z), tf32rf(b.z), tf32rf(a.w), tf32rf(b.w));
}

// ---------------- 512x512 weight transpose + rna + id-permute ----------------
__global__ void transpose512(const float* __restrict__ in, float* __restrict__ out) {
    __shared__ float tile[32][33];
    int x = blockIdx.x * 32 + threadIdx.x;
    int y0 = blockIdx.y * 32;
#pragma unroll
    for (int j = threadIdx.y; j < 32; j += 8)
        tile[j][threadIdx.x] = in[(size_t)(y0 + j) * 512 + x];
    __syncthreads();
    int ox = y0 + threadIdx.x;                      // logical in_dim index (k of GEMM)
    int sx = (ox & ~7) | perm8(ox & 7);             // permuted storage position
    int oy0 = blockIdx.x * 32;
#pragma unroll
    for (int j = threadIdx.y; j < 32; j += 8)
        out[(size_t)(oy0 + j) * 512 + sx] = tf32rf(tile[threadIdx.x][j]);
}

// ---------------- row softmax over 4096, in place, rna output ----------------
__global__ __launch_bounds__(256)
void softmax_kernel(float* __restrict__ S) {
    const size_t row = blockIdx.x;
    float* p = S + row * (size_t)NTOK;
    const int t = threadIdx.x;
    float v[16];
#pragma unroll
    for (int i = 0; i < 16; i++) v[i] = p[t + i * 256];
    float m = v[0];
#pragma unroll
    for (int i = 1; i < 16; i++) m = fmaxf(m, v[i]);
    __shared__ float red[256];
    red[t] = m; __syncthreads();
    for (int s = 128; s > 0; s >>= 1) { if (t < s) red[t] = fmaxf(red[t], red[t + s]); __syncthreads(); }
    m = red[0]; __syncthreads();
    float sum = 0.f;
#pragma unroll
    for (int i = 0; i < 16; i++) { v[i] = __expf(v[i] - m); sum += v[i]; }
    red[t] = sum; __syncthreads();
    for (int s = 128; s > 0; s >>= 1) { if (t < s) red[t] += red[t + s]; __syncthreads(); }
    const float inv = 1.0f / red[0];
#pragma unroll
    for (int i = 0; i < 16; i++) p[t + i * 256] = tf32rf(v[i] * inv);
}

// ---------------- launch ----------------
extern "C" void kernel_launch(void* const* d_in, const int* in_sizes, int n_in,
                              void* d_out, int out_size) {
    const float* qX  = (const float*)d_in[0];
    const float* kX  = (const float*)d_in[1];
    const float* vX  = (const float*)d_in[2];
    const float* W_Q = (const float*)d_in[3];
    const float* b_Q = (const float*)d_in[4];
    const float* W_K = (const float*)d_in[5];
    const float* b_K = (const float*)d_in[6];
    const float* W_V = (const float*)d_in[7];
    const float* b_V = (const float*)d_in[8];
    float* out = (float*)d_out;

    float *Q, *K, *Vt, *S, *Wt;
    cudaGetSymbolAddress((void**)&Q,  g_Q);
    cudaGetSymbolAddress((void**)&K,  g_K);
    cudaGetSymbolAddress((void**)&Vt, g_Vt);
    cudaGetSymbolAddress((void**)&S,  g_S);
    cudaGetSymbolAddress((void**)&Wt, g_Wt);

    cudaFuncSetAttribute(gemm_mma<true,  1>, cudaFuncAttributeMaxDynamicSharedMemorySize, SMEM_TOT);
    cudaFuncSetAttribute(gemm_mma<true,  3>, cudaFuncAttributeMaxDynamicSharedMemorySize, SMEM_TOT);
    cudaFuncSetAttribute(gemm_mma<false, 2>, cudaFuncAttributeMaxDynamicSharedMemorySize, SMEM_TOT);
    cudaFuncSetAttribute(gemm_mma<false, 0>, cudaFuncAttributeMaxDynamicSharedMemorySize, SMEM_TOT);

    const long long sQKV = (long long)NTOK * DIM;
    const long long sS   = (long long)NTOK * NTOK;
    const size_t nin = (size_t)MTOT * DIM;           // 8.39M floats per input

    // rna'd/permuted inputs live in g_S until the scores GEMM overwrites it
    float* qR = S;
    float* kR = S + nin;
    float* vR = S + 2 * nin;

    // 0) prepass inputs + weights
    {
        int n8 = (int)(nin / 8);
        prep_rna_perm<<<(n8 + 255) / 256, 256>>>(qX, qR, n8);
        prep_rna_perm<<<(n8 + 255) / 256, 256>>>(kX, kR, n8);
        prep_rna_perm<<<(n8 + 255) / 256, 256>>>(vX, vR, n8);
        dim3 g(16, 16), b(32, 8);
        transpose512<<<g, b>>>(W_Q, Wt);
        transpose512<<<g, b>>>(W_K, Wt + (size_t)DIM * DIM);
        transpose512<<<g, b>>>(W_V, Wt + 2 * (size_t)DIM * DIM);
    }

    // 1) projections (Q pre-scaled); outputs tf32 + permuted for next stage
    {
        dim3 grid(DIM / BN, MTOT / BM, 1);
        gemm_mma<true, 1><<<grid, 128, SMEM_TOT>>>(qR, Wt, b_Q, Q,
            DIM, DIM, DIM, DIM, SM_SCALE, 0, 0, 0);
        gemm_mma<true, 1><<<grid, 128, SMEM_TOT>>>(kR, Wt + (size_t)DIM * DIM, b_K, K,
            DIM, DIM, DIM, DIM, 1.0f, 0, 0, 0);
        gemm_mma<true, 3><<<grid, 128, SMEM_TOT>>>(vR, Wt + 2 * (size_t)DIM * DIM, b_V, Vt,
            DIM, DIM, DIM, DIM, 1.0f, 0, 0, 0);
    }

    // 2) scores: S[b] = Q[b] @ K[b]^T (scale folded into Q); cols stored token-permuted
    {
        dim3 grid(NTOK / BN, NTOK / BM, NBATCH);
        gemm_mma<false, 2><<<grid, 128, SMEM_TOT>>>(Q, K, nullptr, S,
            NTOK, DIM, DIM, DIM, 1.0f, sQKV, sQKV, sS);
    }

    // 3) softmax (elementwise over permuted cols; rna output)
    softmax_kernel<<<MTOT, 256>>>(S);

    // 4) out[b] = P[b] @ Vt[b]^T (token perm consistent between P cols and Vt cols)
    {
        dim3 grid(DIM / BN, NTOK / BM, NBATCH);
        gemm_mma<false, 0><<<grid, 128, SMEM_TOT>>>(S, Vt, nullptr, out,
            DIM, NTOK, NTOK, NTOK, 1.0f, sS, sQKV, sQKV);
    }
}

// round 6
// speedup vs baseline: 6.7948x; 2.1064x over previous
#include <cuda_runtime.h>
#include <cuda_fp16.h>
#include <cstdint>

#define NBATCH 4
#define NTOK   4096
#define DIM    512
#define MTOT   (NBATCH * NTOK)
#define SM_SCALE 0.044194173824159216f   // 1/sqrt(512)

// ---------------- scratch (half precision) ----------------
__device__ __half g_Q [(size_t)MTOT * DIM];            // 16 MB, cols perm16, pre-scaled
__device__ __half g_K [(size_t)MTOT * DIM];            // 16 MB, cols perm16
__device__ __half g_Vt[(size_t)MTOT * DIM];            // 16 MB, per-batch [dim][tok], tok perm16
__device__ __half g_S [(size_t)NBATCH * NTOK * NTOK];  // 134 MB (hosts prepped inputs pre-scores)
__device__ __half g_Wt[3ULL * DIM * DIM];              // 1.5 MB transposed + perm16

// ---------------- helpers ----------------
// perm16: logical index j in a 16-group -> storage position (pairs (k,k+1,k+8,k+9) contiguous)
__device__ __forceinline__ int pos16(int j) {
    return ((j & 6) << 1) | ((j & 8) >> 2) | (j & 1);
}
__device__ __forceinline__ void mma_f16(float* d, const uint32_t* a, const uint32_t* b) {
    asm volatile(
        "mma.sync.aligned.m16n8k16.row.col.f32.f16.f16.f32 "
        "{%0,%1,%2,%3}, {%4,%5,%6,%7}, {%8,%9}, {%0,%1,%2,%3};"
        : "+f"(d[0]), "+f"(d[1]), "+f"(d[2]), "+f"(d[3])
        : "r"(a[0]), "r"(a[1]), "r"(a[2]), "r"(a[3]), "r"(b[0]), "r"(b[1]));
}
__device__ __forceinline__ uint32_t smem_u32(const void* p) {
    uint32_t r;
    asm("{ .reg .u64 t; cvta.to.shared.u64 t, %1; cvt.u32.u64 %0, t; }" : "=r"(r) : "l"(p));
    return r;
}
__device__ __forceinline__ void cpa16(uint32_t dst, const void* src) {
    asm volatile("cp.async.cg.shared.global [%0], [%1], 16;" :: "r"(dst), "l"(src));
}
#define CP_COMMIT() asm volatile("cp.async.commit_group;" ::: "memory")
#define CP_WAIT2()  asm volatile("cp.async.wait_group 2;" ::: "memory")

// ---------------- tiling ----------------
#define BM 128
#define BN 128
#define BK 32                         // k halves per chunk (2 k16 steps)
#define ROWB 96                       // bytes per smem row (64B data + 32B pad; 12 mod 16 slots)
#define TILE_BYTES (128 * ROWB)       // 12288
#define STAGE_BYTES (2 * TILE_BYTES)  // A + B = 24576
#define NSTAGE 3
#define SMEM_TOT (NSTAGE * STAGE_BYTES)   // 73728

// ---------------- fp16 tensor-core GEMM: C[M,N] = alpha*(A @ B^T + bias) ----------------
// A: [M x K] half row-major (lda halves), B: [N x K] half row-major (ldb halves),
// both stored with perm16 within each 16-wide k-group.
// OM: 0 = fp32 out plain; 1 = half out, col perm16 (Q/K proj); 2 = half out, col perm16 (S);
//     3 = half transposed [dim][tok] out, tok perm16 (V proj).
template <bool BIAS, int OM>
__global__ __launch_bounds__(128, 2)
void gemm_h(const __half* __restrict__ Ag, const __half* __restrict__ Bg,
            const float* __restrict__ bias, void* __restrict__ Cg,
            int N, int K, int lda, int ldb, float alpha,
            long long sA, long long sB, long long sC) {
    extern __shared__ char smem[];
    const uint32_t sbase = smem_u32(smem);

    const int t    = threadIdx.x;
    const int lane = t & 31;
    const int w    = t >> 5;
    const int wm   = (w & 1) * 64;
    const int wn   = (w >> 1) * 64;
    const int m0   = blockIdx.y * BM;
    const int n0   = blockIdx.x * BN;
    const int bz   = blockIdx.z;

    const __half* A = Ag + (long long)bz * sA;
    const __half* B = Bg + (long long)bz * sB;

    // staging: 4 lanes per row (16B each), thread covers rows rbase+32i
    const int rbase = t >> 2;
    const int ch    = t & 3;
    const __half* Arow = A + (long long)m0 * lda + ch * 8;
    const __half* Brow = B + (long long)n0 * ldb + ch * 8;

    auto issue = [&](int c, int buf) {
        const int k0 = c * BK;
        const uint32_t da = sbase + (uint32_t)buf * STAGE_BYTES;
        const uint32_t db = da + TILE_BYTES;
#pragma unroll
        for (int i = 0; i < 4; i++) {
            const int r = rbase + 32 * i;
            cpa16(da + r * ROWB + ch * 16, Arow + (long long)r * lda + k0);
            cpa16(db + r * ROWB + ch * 16, Brow + (long long)r * ldb + k0);
        }
    };

    float acc[4][8][4];
#pragma unroll
    for (int i = 0; i < 4; i++)
#pragma unroll
        for (int j = 0; j < 8; j++)
#pragma unroll
            for (int q = 0; q < 4; q++) acc[i][j][q] = 0.0f;

    const int nchunk = K >> 5;
    issue(0, 0); CP_COMMIT();
    issue(1, 1); CP_COMMIT();
    issue(2, 2); CP_COMMIT();

    const int fr = lane >> 2;
    const int fj = lane & 3;

    for (int c = 0; c < nchunk; c++) {
        const int buf = c % NSTAGE;
        CP_WAIT2();
        __syncthreads();

        const char* As = smem + buf * STAGE_BYTES;
        const char* Bs = As + TILE_BYTES;

#pragma unroll
        for (int ks = 0; ks < 2; ks++) {
            const int off = ks * 32 + 8 * fj;
            uint32_t a[4][4], b[8][2];
#pragma unroll
            for (int ma = 0; ma < 4; ma++) {
                const char* pr = As + (wm + 16 * ma + fr) * ROWB + off;
                uint2 lo = *reinterpret_cast<const uint2*>(pr);
                uint2 hi = *reinterpret_cast<const uint2*>(pr + 8 * ROWB);
                a[ma][0] = lo.x; a[ma][2] = lo.y;
                a[ma][1] = hi.x; a[ma][3] = hi.y;
            }
#pragma unroll
            for (int na = 0; na < 8; na++) {
                uint2 v = *reinterpret_cast<const uint2*>(Bs + (wn + 8 * na + fr) * ROWB + off);
                b[na][0] = v.x; b[na][1] = v.y;
            }
#pragma unroll
            for (int ma = 0; ma < 4; ma++)
#pragma unroll
                for (int na = 0; na < 8; na++)
                    mma_f16(acc[ma][na], a[ma], b[na]);
        }

        __syncthreads();
        if (c + NSTAGE < nchunk) issue(c + NSTAGE, buf);
        CP_COMMIT();
    }

    // ---------------- epilogue ----------------
    const int fp = 2 * fj;
#pragma unroll
    for (int ma = 0; ma < 4; ma++) {
        const int r0 = m0 + wm + ma * 16 + fr;
#pragma unroll
        for (int na = 0; na < 8; na++) {
            const int col = n0 + wn + na * 8 + fp;   // logical col (even)
            float v0 = acc[ma][na][0], v1 = acc[ma][na][1];
            float v2 = acc[ma][na][2], v3 = acc[ma][na][3];
            if (BIAS) {
                const float b0 = bias[col], b1 = bias[col + 1];
                v0 += b0; v1 += b1; v2 += b0; v3 += b1;
            }
            v0 *= alpha; v1 *= alpha; v2 *= alpha; v3 *= alpha;

            if (OM == 3) {
                // transposed: out[b][dim=col][tok], tok perm16'd. r0&15 = fr (<8)
                const int tokb = (r0 & (NTOK - 1)) & ~15;
                const int tp   = pos16(r0 & 15);
                __half* o = (__half*)Cg + (long long)(r0 >> 12) * ((long long)DIM * NTOK);
                o[(long long)col * NTOK + tokb + tp]           = __float2half_rn(v0);
                o[(long long)(col + 1) * NTOK + tokb + tp]     = __float2half_rn(v1);
                o[(long long)col * NTOK + tokb + tp + 2]       = __float2half_rn(v2);
                o[(long long)(col + 1) * NTOK + tokb + tp + 2] = __float2half_rn(v3);
            } else if (OM == 1 || OM == 2) {
                const int scol = (col & ~15) | pos16(col & 15);   // even -> half2-aligned
                __half* o = (__half*)Cg + (long long)bz * sC;
                *reinterpret_cast<__half2*>(o + (long long)r0 * N + scol) =
                    __floats2half2_rn(v0, v1);
                *reinterpret_cast<__half2*>(o + (long long)(r0 + 8) * N + scol) =
                    __floats2half2_rn(v2, v3);
            } else {
                float* o = (float*)Cg + (long long)bz * sC;
                *reinterpret_cast<float2*>(o + (long long)r0 * N + col)       = make_float2(v0, v1);
                *reinterpret_cast<float2*>(o + (long long)(r0 + 8) * N + col) = make_float2(v2, v3);
            }
        }
    }
}

// ---------------- input prepass: fp32 -> half with perm16 (one 16-group / thread) --------
__global__ __launch_bounds__(256)
void prep_h(const float* __restrict__ in, __half* __restrict__ out, int n16) {
    int i = blockIdx.x * 256 + threadIdx.x;
    if (i >= n16) return;
    const float4* p = reinterpret_cast<const float4*>(in) + 4 * (size_t)i;
    float L[16];
    *reinterpret_cast<float4*>(L)      = p[0];
    *reinterpret_cast<float4*>(L + 4)  = p[1];
    *reinterpret_cast<float4*>(L + 8)  = p[2];
    *reinterpret_cast<float4*>(L + 12) = p[3];
    __half2 h[8];
#pragma unroll
    for (int tt = 0; tt < 4; tt++) {
        h[2 * tt]     = __floats2half2_rn(L[2 * tt],     L[2 * tt + 1]);
        h[2 * tt + 1] = __floats2half2_rn(L[2 * tt + 8], L[2 * tt + 9]);
    }
    uint4* o = reinterpret_cast<uint4*>(out + 16 * (size_t)i);
    o[0] = *reinterpret_cast<uint4*>(h);
    o[1] = *reinterpret_cast<uint4*>(h + 4);
}

// ---------------- 512x512 weight transpose -> half + perm16 on in_dim ----------------
__global__ void transpose512h(const float* __restrict__ in, __half* __restrict__ out) {
    __shared__ float tile[32][33];
    int x = blockIdx.x * 32 + threadIdx.x;
    int y0 = blockIdx.y * 32;
#pragma unroll
    for (int j = threadIdx.y; j < 32; j += 8)
        tile[j][threadIdx.x] = in[(size_t)(y0 + j) * 512 + x];
    __syncthreads();
    int ox = y0 + threadIdx.x;                       // logical in_dim (k)
    int sx = (ox & ~15) | pos16(ox & 15);
    int oy0 = blockIdx.x * 32;
#pragma unroll
    for (int j = threadIdx.y; j < 32; j += 8)
        out[(size_t)(oy0 + j) * 512 + sx] = __float2half_rn(tile[threadIdx.x][j]);
}

// ---------------- row softmax over 4096 halves, in place ----------------
__global__ __launch_bounds__(256)
void softmax_h(__half* __restrict__ S) {
    __half* p = S + (size_t)blockIdx.x * NTOK;
    const int t = threadIdx.x;
    uint4 u0 = reinterpret_cast<uint4*>(p)[2 * t];
    uint4 u1 = reinterpret_cast<uint4*>(p)[2 * t + 1];
    float v[16];
    {
        const __half2* h0 = reinterpret_cast<const __half2*>(&u0);
        const __half2* h1 = reinterpret_cast<const __half2*>(&u1);
#pragma unroll
        for (int i = 0; i < 4; i++) {
            float2 f = __half22float2(h0[i]); v[2 * i] = f.x; v[2 * i + 1] = f.y;
            float2 g = __half22float2(h1[i]); v[8 + 2 * i] = g.x; v[9 + 2 * i] = g.y;
        }
    }
    float m = v[0];
#pragma unroll
    for (int i = 1; i < 16; i++) m = fmaxf(m, v[i]);
    __shared__ float red[256];
    red[t] = m; __syncthreads();
    for (int s = 128; s > 0; s >>= 1) { if (t < s) red[t] = fmaxf(red[t], red[t + s]); __syncthreads(); }
    m = red[0]; __syncthreads();
    float sum = 0.f;
#pragma unroll
    for (int i = 0; i < 16; i++) { v[i] = __expf(v[i] - m); sum += v[i]; }
    red[t] = sum; __syncthreads();
    for (int s = 128; s > 0; s >>= 1) { if (t < s) red[t] += red[t + s]; __syncthreads(); }
    const float inv = 1.0f / red[0];
    __half2 h[8];
#pragma unroll
    for (int i = 0; i < 8; i++)
        h[i] = __floats2half2_rn(v[2 * i] * inv, v[2 * i + 1] * inv);
    reinterpret_cast<uint4*>(p)[2 * t]     = *reinterpret_cast<uint4*>(h);
    reinterpret_cast<uint4*>(p)[2 * t + 1] = *reinterpret_cast<uint4*>(h + 4);
}

// ---------------- launch ----------------
extern "C" void kernel_launch(void* const* d_in, const int* in_sizes, int n_in,
                              void* d_out, int out_size) {
    const float* qX  = (const float*)d_in[0];
    const float* kX  = (const float*)d_in[1];
    const float* vX  = (const float*)d_in[2];
    const float* W_Q = (const float*)d_in[3];
    const float* b_Q = (const float*)d_in[4];
    const float* W_K = (const float*)d_in[5];
    const float* b_K = (const float*)d_in[6];
    const float* W_V = (const float*)d_in[7];
    const float* b_V = (const float*)d_in[8];
    float* out = (float*)d_out;

    __half *Q, *K, *Vt, *S, *Wt;
    cudaGetSymbolAddress((void**)&Q,  g_Q);
    cudaGetSymbolAddress((void**)&K,  g_K);
    cudaGetSymbolAddress((void**)&Vt, g_Vt);
    cudaGetSymbolAddress((void**)&S,  g_S);
    cudaGetSymbolAddress((void**)&Wt, g_Wt);

    cudaFuncSetAttribute(gemm_h<true,  1>, cudaFuncAttributeMaxDynamicSharedMemorySize, SMEM_TOT);
    cudaFuncSetAttribute(gemm_h<true,  3>, cudaFuncAttributeMaxDynamicSharedMemorySize, SMEM_TOT);
    cudaFuncSetAttribute(gemm_h<false, 2>, cudaFuncAttributeMaxDynamicSharedMemorySize, SMEM_TOT);
    cudaFuncSetAttribute(gemm_h<false, 0>, cudaFuncAttributeMaxDynamicSharedMemorySize, SMEM_TOT);

    const long long sQKV = (long long)NTOK * DIM;
    const long long sS   = (long long)NTOK * NTOK;
    const size_t nin = (size_t)MTOT * DIM;

    // prepped half inputs live in g_S until scores GEMM overwrites it
    __half* qR = S;
    __half* kR = S + nin;
    __half* vR = S + 2 * nin;

    // 0) prepass inputs + weights
    {
        int n16 = (int)(nin / 16);
        prep_h<<<(n16 + 255) / 256, 256>>>(qX, qR, n16);
        prep_h<<<(n16 + 255) / 256, 256>>>(kX, kR, n16);
        prep_h<<<(n16 + 255) / 256, 256>>>(vX, vR, n16);
        dim3 g(16, 16), b(32, 8);
        transpose512h<<<g, b>>>(W_Q, Wt);
        transpose512h<<<g, b>>>(W_K, Wt + (size_t)DIM * DIM);
        transpose512h<<<g, b>>>(W_V, Wt + 2 * (size_t)DIM * DIM);
    }

    // 1) projections (Q pre-scaled); outputs half + perm16 for next-stage k
    {
        dim3 grid(DIM / BN, MTOT / BM, 1);
        gemm_h<true, 1><<<grid, 128, SMEM_TOT>>>(qR, Wt, b_Q, Q,
            DIM, DIM, DIM, DIM, SM_SCALE, 0, 0, 0);
        gemm_h<true, 1><<<grid, 128, SMEM_TOT>>>(kR, Wt + (size_t)DIM * DIM, b_K, K,
            DIM, DIM, DIM, DIM, 1.0f, 0, 0, 0);
        gemm_h<true, 3><<<grid, 128, SMEM_TOT>>>(vR, Wt + 2 * (size_t)DIM * DIM, b_V, Vt,
            DIM, DIM, DIM, DIM, 1.0f, 0, 0, 0);
    }

    // 2) scores: S[b] = Q[b] @ K[b]^T (scale folded into Q); cols stored tok-perm16
    {
        dim3 grid(NTOK / BN, NTOK / BM, NBATCH);
        gemm_h<false, 2><<<grid, 128, SMEM_TOT>>>(Q, K, nullptr, S,
            NTOK, DIM, DIM, DIM, 1.0f, sQKV, sQKV, sS);
    }

    // 3) softmax (perm-invariant row reduction)
    softmax_h<<<MTOT, 256>>>(S);

    // 4) out[b] = P[b] @ Vt[b]^T (tok perm consistent between P cols and Vt cols)
    {
        dim3 grid(DIM / BN, NTOK / BM, NBATCH);
        gemm_h<false, 0><<<grid, 128, SMEM_TOT>>>(S, Vt, nullptr, out,
            DIM, NTOK, NTOK, NTOK, 1.0f, sS, sQKV, sQKV);
    }
}